// round 15
// baseline (speedup 1.0000x reference)
#include <cuda_runtime.h>
#include <math.h>

#define BB 256
#define LL 256
#define VV 14
#define EMBD 512
#define HH 128
#define OC 256
#define NP 196
#define NPP 256          // padded pair stride
#define KLIN 32768       // OC*HH
#define NJ 128
#define SPLITK 128
#define KC (KLIN/SPLITK) // 256 -> 2 output channels per split-K chunk

typedef unsigned long long ull;

// dynamic smem layout for k_gemmF (As rows padded to 132 floats)
#define SM_AS    0                       // 2*16*132*4 = 16896
#define SM_BS    16896                   // 2*16*128*4 = 16384
#define SM_P2    33280                   // 6*256*4 = 6144
#define SM_SPI   39424                   // 128*132 = 16896
#define SM_BIAS  56320                   // 8
#define SM_TOTAL 56328

// ---------------- scratch ---------------------------------------------------
__device__ float g_poolT_e[EMBD*NPP];
__device__ float g_poolT_f[EMBD*NPP];
__device__ float g_pbpart[4*2*3*OC*NPP];   // [cs][br][kh][o][p]
__device__ float g_P2[2*3*OC*NPP];         // [br][kh][o][p]
__device__ unsigned char g_pi8T[2*HH*BB];  // [br][h][b] pair idx as uint8
__device__ float g_partial[SPLITK*BB*NJ];  // 16.8MB
__device__ float g_Wsum[3*64*128];
__device__ float g_Lmid[64*256];

// ---------------- f32x2 helpers --------------------------------------------
__device__ __forceinline__ ull pk2(float lo, float hi){
    ull r; asm("mov.b64 %0, {%1, %2};" : "=l"(r) : "f"(lo), "f"(hi)); return r;
}
__device__ __forceinline__ void upk2(ull v, float& lo, float& hi){
    asm("mov.b64 {%0, %1}, %2;" : "=f"(lo), "=f"(hi) : "l"(v));
}
__device__ __forceinline__ void ffma2(ull& c, ull a, ull b){
    asm("fma.rn.f32x2 %0, %1, %2, %0;" : "+l"(c) : "l"(a), "l"(b));
}

// ---------------- pooled-pair LUT, both branches ----------------------------
__global__ void k_poolT2(const float* __restrict__ eemb, const float* __restrict__ femb){
    int idx = blockIdx.x*256 + threadIdx.x;        // < 2*EMBD*NPP
    int br = idx / (EMBD*NPP);
    int r  = idx % (EMBD*NPP);
    int c = r >> 8, p = r & 255;
    const float* emb = br ? femb : eemb;
    float v = 0.f;
    if (p < NP){
        int t1 = p / VV, t2 = p % VV;
        v = fmaxf(emb[t1*EMBD + c], emb[t2*EMBD + c]);
    }
    (br ? g_poolT_f : g_poolT_e)[c*NPP + p] = v;
}

// ---------------- pbuild: P2 partials, c-split x4, both branches ------------
__global__ __launch_bounds__(512) void k_pbuild2(const float* __restrict__ ecw,
                                                 const float* __restrict__ fcw){
    int ot = blockIdx.x;          // 0..31 -> 8 o's
    int cs = blockIdx.y;          // 0..3  -> 128 c's
    int br = blockIdx.z;          // 0..1
    const float* cw    = br ? fcw : ecw;
    const float* poolT = br ? g_poolT_f : g_poolT_e;
    int o0 = ot*8, c0 = cs*128;
    __shared__ float ws[8*3*128];                 // [oi][kh][c]
    int tid = threadIdx.x;
    for (int e = tid; e < 3072; e += 512){
        int oi = e / 384, r = e % 384, kh = r >> 7, c = r & 127;
        ws[e] = cw[((size_t)(o0+oi)*EMBD + (c0+c))*9 + 1 + kh*3];
    }
    __syncthreads();
    int pg = tid & 63, oi = tid >> 6;
    int p0 = pg*4;
    ull a0=0,a1=0,a2=0,a3=0,a4=0,a5=0;   // [kh][pair]
    const float* pt  = poolT + (size_t)c0*NPP + p0;
    const float* wsp = ws + oi*384;
    #pragma unroll 4
    for (int c = 0; c < 128; c++){
        float4 pv = *(const float4*)(pt + (size_t)c*NPP);
        ull pa0 = pk2(pv.x, pv.y), pa1 = pk2(pv.z, pv.w);
        float w0 = wsp[c], w1 = wsp[128+c], w2 = wsp[256+c];
        ull b0 = pk2(w0,w0), b1 = pk2(w1,w1), b2 = pk2(w2,w2);
        ffma2(a0, pa0, b0); ffma2(a1, pa1, b0);
        ffma2(a2, pa0, b1); ffma2(a3, pa1, b1);
        ffma2(a4, pa0, b2); ffma2(a5, pa1, b2);
    }
    size_t base = (((size_t)(cs*2 + br)*3)*OC + (o0+oi))*NPP + p0;
    *(ulonglong2*)(g_pbpart + base)            = make_ulonglong2(a0, a1);
    *(ulonglong2*)(g_pbpart + base + OC*NPP)   = make_ulonglong2(a2, a3);
    *(ulonglong2*)(g_pbpart + base + 2*OC*NPP) = make_ulonglong2(a4, a5);
}

// ---------------- prep: P2 reduce + enemy pairidx + wsum + lmid -------------
__global__ void k_prep(const int* __restrict__ x, const float* __restrict__ mcw,
                       const float* __restrict__ mlw){
    int blk = blockIdx.x;
    if (blk < 1536){
        int idx = blk*256 + threadIdx.x;           // < 2*3*OC*NPP
        int br = idx / (3*OC*NPP);
        int inner = idx % (3*OC*NPP);
        float s = g_pbpart[(0*2+br)*(3*OC*NPP) + inner]
                + g_pbpart[(1*2+br)*(3*OC*NPP) + inner]
                + g_pbpart[(2*2+br)*(3*OC*NPP) + inner]
                + g_pbpart[(3*2+br)*(3*OC*NPP) + inner];
        g_P2[idx] = s;
    } else if (blk < 1664){
        int idx = (blk - 1536)*256 + threadIdx.x;  // < HH*BB, idx = h*BB + b
        int b = idx & 255, h = idx >> 8;
        g_pi8T[idx] = (unsigned char)(x[b*LL + 2*h]*VV + x[b*LL + 2*h + 1]);
    } else if (blk < 1760){
        int idx = (blk - 1664)*256 + threadIdx.x;  // < 3*64*128
        int v = idx / 8192;
        int rem = idx % 8192;
        int base = rem*9 + 1;
        float w0 = mcw[base], w1 = mcw[base+3], w2 = mcw[base+6];
        g_Wsum[idx] = (v==0) ? (w1+w2) : (v==1) ? (w0+w1+w2) : (w0+w1);
    } else {
        int idx = (blk - 1760)*256 + threadIdx.x;  // < 64*256
        int o = idx >> 8, j = idx & 255;
        float s = 0.f;
        for (int h=1; h<127; h++) s += mlw[(size_t)(o*128 + h)*256 + j];
        g_Lmid[idx] = s;
    }
}

// ---------------- fused conv+GEMM, split-K, f32x2, double-buffered ----------
// A-builder threads now own 8 CONTIGUOUS m (uchar4 spi reads, float4 As stores)
__global__ __launch_bounds__(256) void k_gemmF(int which, const float* __restrict__ W,
                                               const float* __restrict__ bias){
    extern __shared__ char dyn[];
    float (*As)[16][132]      = (float(*)[16][132])(dyn + SM_AS);
    float (*Bs)[16][128]      = (float(*)[16][128])(dyn + SM_BS);
    float (*sP2)[256]         = (float(*)[256])(dyn + SM_P2);
    unsigned char (*spi)[132] = (unsigned char(*)[132])(dyn + SM_SPI);
    float* sbias              = (float*)(dyn + SM_BIAS);

    int tid = threadIdx.x;
    int m0 = blockIdx.x * 128;
    int k0 = blockIdx.y * KC;
    int o0 = k0 >> 7;
    int lk = tid & 15, lm = tid >> 4;
    int mb = lm*8;                   // contiguous 8-m group for the A-builder
    int bj = tid & 127, bk = tid >> 7;
    int tx = tid & 15, ty = tid >> 4;

    const float* P2 = g_P2 + (size_t)which*(3*OC*NPP);
    for (int e = tid; e < 1536; e += 256){
        int kh = e / 512, r = e % 512, oi = r >> 8, p = r & 255;
        sP2[kh*2 + oi][p] = P2[(size_t)kh*OC*NPP + (o0+oi)*NPP + p];
    }
    const unsigned char* piT = g_pi8T + (size_t)which*(HH*BB);
    for (int e = tid; e < 4096; e += 256){
        int h = e >> 5, g = e & 31;
        *(uchar4*)&spi[h][g*4] = *(const uchar4*)(piT + h*BB + m0 + g*4);
    }
    if (tid < 2) sbias[tid] = bias[o0 + tid];
    __syncthreads();

    ull acc[4][8];
    #pragma unroll
    for (int i=0;i<4;i++)
        #pragma unroll
        for (int j=0;j<8;j++) acc[i][j] = 0ull;

    float ra[8], rb[8];
    auto computeA = [&](int t, float* r){
        int k = k0 + t + lk;
        int h = k & 127;
        int oi = (k >> 7) - o0;
        const float* p2a = sP2[0 + oi];
        const float* p2b = sP2[2 + oi];
        const float* p2c = sP2[4 + oi];
        float vb = sbias[oi];
        bool hasA = (h > 0), hasC = (h < 127);
        uchar4 qb0 = *(const uchar4*)&spi[h][mb];
        uchar4 qb1 = *(const uchar4*)&spi[h][mb+4];
        uchar4 qa0 = qb0, qa1 = qb1, qc0 = qb0, qc1 = qb1;
        if (hasA){ qa0 = *(const uchar4*)&spi[h-1][mb]; qa1 = *(const uchar4*)&spi[h-1][mb+4]; }
        if (hasC){ qc0 = *(const uchar4*)&spi[h+1][mb]; qc1 = *(const uchar4*)&spi[h+1][mb+4]; }
        unsigned char ia[8] = {qa0.x,qa0.y,qa0.z,qa0.w,qa1.x,qa1.y,qa1.z,qa1.w};
        unsigned char ib[8] = {qb0.x,qb0.y,qb0.z,qb0.w,qb1.x,qb1.y,qb1.z,qb1.w};
        unsigned char ic[8] = {qc0.x,qc0.y,qc0.z,qc0.w,qc1.x,qc1.y,qc1.z,qc1.w};
        #pragma unroll
        for (int i=0;i<8;i++){
            float v = vb;
            if (hasA) v += p2a[ia[i]];
            v += p2b[ib[i]];
            if (hasC) v += p2c[ic[i]];
            r[i] = v;
        }
    };
    auto storeA = [&](int b2, float* r){
        *(float4*)&As[b2][lk][mb]     = make_float4(r[0], r[1], r[2], r[3]);
        *(float4*)&As[b2][lk][mb + 4] = make_float4(r[4], r[5], r[6], r[7]);
    };

    computeA(0, ra);
    #pragma unroll
    for (int i=0;i<8;i++) rb[i] = W[(size_t)(k0 + bk + i*2)*NJ + bj];
    storeA(0, ra);
    #pragma unroll
    for (int i=0;i<8;i++) Bs[0][bk + i*2][bj] = rb[i];
    __syncthreads();

    int buf = 0;
    for (int t = 16; t < KC; t += 16){
        computeA(t, ra);
        #pragma unroll
        for (int i=0;i<8;i++) rb[i] = W[(size_t)(k0 + t + bk + i*2)*NJ + bj];
        #pragma unroll
        for (int kk=0; kk<16; kk++){
            ulonglong2 a01 = *(const ulonglong2*)&As[buf][kk][ty*8];
            ulonglong2 a23 = *(const ulonglong2*)&As[buf][kk][ty*8 + 4];
            float4 b0 = *(const float4*)&Bs[buf][kk][tx*4];
            float4 b1 = *(const float4*)&Bs[buf][kk][64 + tx*4];
            ull ap[4] = { a01.x, a01.y, a23.x, a23.y };
            ull bd[8] = { pk2(b0.x,b0.x), pk2(b0.y,b0.y),
                          pk2(b0.z,b0.z), pk2(b0.w,b0.w),
                          pk2(b1.x,b1.x), pk2(b1.y,b1.y),
                          pk2(b1.z,b1.z), pk2(b1.w,b1.w) };
            #pragma unroll
            for (int i=0;i<4;i++)
                #pragma unroll
                for (int j=0;j<8;j++)
                    ffma2(acc[i][j], ap[i], bd[j]);
        }
        storeA(buf^1, ra);
        #pragma unroll
        for (int i=0;i<8;i++) Bs[buf^1][bk + i*2][bj] = rb[i];
        __syncthreads();
        buf ^= 1;
    }
    #pragma unroll
    for (int kk=0; kk<16; kk++){
        ulonglong2 a01 = *(const ulonglong2*)&As[buf][kk][ty*8];
        ulonglong2 a23 = *(const ulonglong2*)&As[buf][kk][ty*8 + 4];
        float4 b0 = *(const float4*)&Bs[buf][kk][tx*4];
        float4 b1 = *(const float4*)&Bs[buf][kk][64 + tx*4];
        ull ap[4] = { a01.x, a01.y, a23.x, a23.y };
        ull bd[8] = { pk2(b0.x,b0.x), pk2(b0.y,b0.y),
                      pk2(b0.z,b0.z), pk2(b0.w,b0.w),
                      pk2(b1.x,b1.x), pk2(b1.y,b1.y),
                      pk2(b1.z,b1.z), pk2(b1.w,b1.w) };
        #pragma unroll
        for (int i=0;i<4;i++)
            #pragma unroll
            for (int j=0;j<8;j++)
                ffma2(acc[i][j], ap[i], bd[j]);
    }

    float* outp = g_partial + (size_t)blockIdx.y * (BB*NJ);
    #pragma unroll
    for (int i=0;i<4;i++){
        int mlo = m0 + ty*8 + 2*i;
        float rlo[8], rhi[8];
        #pragma unroll
        for (int j=0;j<8;j++) upk2(acc[i][j], rlo[j], rhi[j]);
        *(float4*)&outp[(size_t)mlo*NJ + tx*4]          = make_float4(rlo[0],rlo[1],rlo[2],rlo[3]);
        *(float4*)&outp[(size_t)mlo*NJ + 64 + tx*4]     = make_float4(rlo[4],rlo[5],rlo[6],rlo[7]);
        *(float4*)&outp[(size_t)(mlo+1)*NJ + tx*4]      = make_float4(rhi[0],rhi[1],rhi[2],rhi[3]);
        *(float4*)&outp[(size_t)(mlo+1)*NJ + 64 + tx*4] = make_float4(rhi[4],rhi[5],rhi[6],rhi[7]);
    }
}

// ---------------- mid: reduce + softmax + manip conv + lin + tokens + pair --
__global__ __launch_bounds__(256) void k_mid(const float* __restrict__ bias,
                                             const float* __restrict__ mcb,
                                             const float* __restrict__ mlw,
                                             const float* __restrict__ mlb){
    __shared__ float red[128];
    __shared__ float eo[128];
    __shared__ float rr[192];
    __shared__ unsigned char stok[256];
    int b = blockIdx.x, t = threadIdx.x;
    float v = 0.f;
    if (t < 128){
        float s = bias[t];
        #pragma unroll 8
        for (int kz=0; kz<SPLITK; kz++) s += g_partial[(size_t)(kz*BB + b)*NJ + t];
        v = s;
        red[t] = v;
    }
    __syncthreads();
    for (int st=64; st; st>>=1){ if (t < st) red[t] = fmaxf(red[t], red[t+st]); __syncthreads(); }
    float mx = red[0]; __syncthreads();
    float e = 0.f;
    if (t < 128){ e = expf(v - mx); red[t] = e; }
    __syncthreads();
    for (int st=64; st; st>>=1){ if (t < st) red[t] += red[t+st]; __syncthreads(); }
    if (t < 128) eo[t] = e / red[0];
    __syncthreads();
    if (t < 192){
        int vv = t >> 6, o = t & 63;
        const float* ws = g_Wsum + vv*8192 + o*128;
        float acc = mcb[o];
        for (int c=0;c<128;c++) acc = fmaf(eo[c], ws[c], acc);
        rr[vv*64 + o] = fmaxf(acc, 0.f);
    }
    __syncthreads();
    {
        int j = t;
        float s = mlb[j];
        for (int o=0; o<64; o++){
            s = fmaf(rr[o],       mlw[(size_t)o*32768 + j],          s);
            s = fmaf(rr[64 + o],  g_Lmid[o*256 + j],                 s);
            s = fmaf(rr[128 + o], mlw[(size_t)o*32768 + 32512 + j],  s);
        }
        int tk = (int)floorf(fabsf(s) * 100.0f);
        stok[j] = (unsigned char)(tk % VV);
    }
    __syncthreads();
    if (t < 128)
        g_pi8T[HH*BB + t*BB + b] = (unsigned char)(stok[2*t]*VV + stok[2*t+1]);
}

// ---------------- friend: reduce + final linear + softmax -------------------
__global__ void k_redlin2(const float* __restrict__ bias, const float* __restrict__ w2,
                          const float* __restrict__ b2, float* __restrict__ out){
    __shared__ float f[128];
    int b = blockIdx.x, t = threadIdx.x;
    float s = bias[t];
    #pragma unroll 8
    for (int kz=0; kz<SPLITK; kz++) s += g_partial[(size_t)(kz*BB + b)*NJ + t];
    f[t] = s; __syncthreads();
    if (t < 32){
        float logit = -INFINITY;
        if (t < VV){
            logit = b2[t];
            for (int j=0; j<128; j++) logit = fmaf(f[j], w2[j*VV + t], logit);
        }
        float mx = logit;
        for (int off=16; off; off>>=1) mx = fmaxf(mx, __shfl_xor_sync(0xffffffffu, mx, off));
        float e = (t < VV) ? expf(logit - mx) : 0.f;
        float sm = e;
        for (int off=16; off; off>>=1) sm += __shfl_xor_sync(0xffffffffu, sm, off);
        if (t < VV) out[b*VV + t] = e / sm;
    }
}

// ---------------- launch ----------------------------------------------------
extern "C" void kernel_launch(void* const* d_in, const int* in_sizes, int n_in,
                              void* d_out, int out_size){
    const int*   x    = (const int*)  d_in[0];
    const float* eemb = (const float*)d_in[1];
    const float* ecw  = (const float*)d_in[2];
    const float* ecb  = (const float*)d_in[3];
    const float* elw  = (const float*)d_in[4];
    const float* elb  = (const float*)d_in[5];
    // d_in[6] rand_proj: dead (fog_of_war == identity permutation)
    const float* mcw  = (const float*)d_in[7];
    const float* mcb  = (const float*)d_in[8];
    const float* mlw  = (const float*)d_in[9];
    const float* mlb  = (const float*)d_in[10];
    const float* femb = (const float*)d_in[11];
    const float* fcw  = (const float*)d_in[12];
    const float* fcb  = (const float*)d_in[13];
    const float* flw1 = (const float*)d_in[14];
    const float* flb1 = (const float*)d_in[15];
    const float* flw2 = (const float*)d_in[16];
    const float* flb2 = (const float*)d_in[17];
    float* out = (float*)d_out;

    cudaFuncSetAttribute(k_gemmF, cudaFuncAttributeMaxDynamicSharedMemorySize, SM_TOTAL);

    k_poolT2<<<(2*EMBD*NPP)/256, 256>>>(eemb, femb);           // 1
    k_pbuild2<<<dim3(32,4,2), 512>>>(ecw, fcw);                // 2
    k_prep<<<1824, 256>>>(x, mcw, mlw);                        // 3

    k_gemmF<<<dim3(2, SPLITK), 256, SM_TOTAL>>>(0, elw, ecb);  // 4 <- profiled
    k_mid<<<BB, 256>>>(elb, mcb, mlw, mlb);                    // 5

    k_gemmF<<<dim3(2, SPLITK), 256, SM_TOTAL>>>(1, flw1, fcb); // 6
    k_redlin2<<<BB, 128>>>(flb1, flw2, flb2, out);             // 7
}

// round 17
// speedup vs baseline: 1.1527x; 1.1527x over previous
#include <cuda_runtime.h>
#include <math.h>
#include <stdint.h>

#define BB 256
#define LL 256
#define VV 14
#define EMBD 512
#define HH 128
#define OC 256
#define NP 196
#define NPP 256          // padded pair stride
#define KLIN 32768       // OC*HH
#define NJ 128
#define SPLITK 128
#define KC (KLIN/SPLITK) // 256 -> 2 output channels per split-K chunk

typedef unsigned long long ull;

// dynamic smem layout for k_gemmF (As rows padded to 132 floats)
#define SM_AS    0                       // 2*16*132*4 = 16896
#define SM_BS    16896                   // 2*16*128*4 = 16384
#define SM_P2    33280                   // 6*256*4 = 6144
#define SM_SPI   39424                   // 128*132 = 16896
#define SM_BIAS  56320                   // 8
#define SM_TOTAL 56328

// ---------------- scratch ---------------------------------------------------
__device__ float g_poolT_e[EMBD*NPP];
__device__ float g_poolT_f[EMBD*NPP];
__device__ float g_pbpart[4*2*3*OC*NPP];   // [cs][br][kh][o][p]
__device__ float g_P2[2*3*OC*NPP];         // [br][kh][o][p]
__device__ unsigned char g_pi8T[2*HH*BB];  // [br][h][b] pair idx as uint8
__device__ float g_partial[SPLITK*BB*NJ];  // 16.8MB
__device__ float g_Wsum[3*64*128];
__device__ float g_Lmid[64*256];

// ---------------- f32x2 helpers --------------------------------------------
__device__ __forceinline__ ull pk2(float lo, float hi){
    ull r; asm("mov.b64 %0, {%1, %2};" : "=l"(r) : "f"(lo), "f"(hi)); return r;
}
__device__ __forceinline__ void upk2(ull v, float& lo, float& hi){
    asm("mov.b64 {%0, %1}, %2;" : "=f"(lo), "=f"(hi) : "l"(v));
}
__device__ __forceinline__ void ffma2(ull& c, ull a, ull b){
    asm("fma.rn.f32x2 %0, %1, %2, %0;" : "+l"(c) : "l"(a), "l"(b));
}

// ---------------- pooled-pair LUT, both branches ----------------------------
__global__ void k_poolT2(const float* __restrict__ eemb, const float* __restrict__ femb){
    int idx = blockIdx.x*256 + threadIdx.x;        // < 2*EMBD*NPP
    int br = idx / (EMBD*NPP);
    int r  = idx % (EMBD*NPP);
    int c = r >> 8, p = r & 255;
    const float* emb = br ? femb : eemb;
    float v = 0.f;
    if (p < NP){
        int t1 = p / VV, t2 = p % VV;
        v = fmaxf(emb[t1*EMBD + c], emb[t2*EMBD + c]);
    }
    (br ? g_poolT_f : g_poolT_e)[c*NPP + p] = v;
}

// ---------------- pbuild: P2 partials, c-split x4, both branches ------------
__global__ __launch_bounds__(512) void k_pbuild2(const float* __restrict__ ecw,
                                                 const float* __restrict__ fcw){
    int ot = blockIdx.x;          // 0..31 -> 8 o's
    int cs = blockIdx.y;          // 0..3  -> 128 c's
    int br = blockIdx.z;          // 0..1
    const float* cw    = br ? fcw : ecw;
    const float* poolT = br ? g_poolT_f : g_poolT_e;
    int o0 = ot*8, c0 = cs*128;
    __shared__ float ws[8*3*128];                 // [oi][kh][c]
    int tid = threadIdx.x;
    for (int e = tid; e < 3072; e += 512){
        int oi = e / 384, r = e % 384, kh = r >> 7, c = r & 127;
        ws[e] = cw[((size_t)(o0+oi)*EMBD + (c0+c))*9 + 1 + kh*3];
    }
    __syncthreads();
    int pg = tid & 63, oi = tid >> 6;
    int p0 = pg*4;
    ull a0=0,a1=0,a2=0,a3=0,a4=0,a5=0;   // [kh][pair]
    const float* pt  = poolT + (size_t)c0*NPP + p0;
    const float* wsp = ws + oi*384;
    #pragma unroll 4
    for (int c = 0; c < 128; c++){
        float4 pv = *(const float4*)(pt + (size_t)c*NPP);
        ull pa0 = pk2(pv.x, pv.y), pa1 = pk2(pv.z, pv.w);
        float w0 = wsp[c], w1 = wsp[128+c], w2 = wsp[256+c];
        ull b0 = pk2(w0,w0), b1 = pk2(w1,w1), b2 = pk2(w2,w2);
        ffma2(a0, pa0, b0); ffma2(a1, pa1, b0);
        ffma2(a2, pa0, b1); ffma2(a3, pa1, b1);
        ffma2(a4, pa0, b2); ffma2(a5, pa1, b2);
    }
    size_t base = (((size_t)(cs*2 + br)*3)*OC + (o0+oi))*NPP + p0;
    *(ulonglong2*)(g_pbpart + base)            = make_ulonglong2(a0, a1);
    *(ulonglong2*)(g_pbpart + base + OC*NPP)   = make_ulonglong2(a2, a3);
    *(ulonglong2*)(g_pbpart + base + 2*OC*NPP) = make_ulonglong2(a4, a5);
}

// ---------------- prep: P2 reduce + enemy pairidx + wsum + lmid -------------
__global__ void k_prep(const int* __restrict__ x, const float* __restrict__ mcw,
                       const float* __restrict__ mlw){
    int blk = blockIdx.x;
    if (blk < 1536){
        int idx = blk*256 + threadIdx.x;           // < 2*3*OC*NPP
        int br = idx / (3*OC*NPP);
        int inner = idx % (3*OC*NPP);
        float s = g_pbpart[(0*2+br)*(3*OC*NPP) + inner]
                + g_pbpart[(1*2+br)*(3*OC*NPP) + inner]
                + g_pbpart[(2*2+br)*(3*OC*NPP) + inner]
                + g_pbpart[(3*2+br)*(3*OC*NPP) + inner];
        g_P2[idx] = s;
    } else if (blk < 1664){
        int idx = (blk - 1536)*256 + threadIdx.x;  // < HH*BB, idx = h*BB + b
        int b = idx & 255, h = idx >> 8;
        g_pi8T[idx] = (unsigned char)(x[b*LL + 2*h]*VV + x[b*LL + 2*h + 1]);
    } else if (blk < 1760){
        int idx = (blk - 1664)*256 + threadIdx.x;  // < 3*64*128
        int v = idx / 8192;
        int rem = idx % 8192;
        int base = rem*9 + 1;
        float w0 = mcw[base], w1 = mcw[base+3], w2 = mcw[base+6];
        g_Wsum[idx] = (v==0) ? (w1+w2) : (v==1) ? (w0+w1+w2) : (w0+w1);
    } else {
        int idx = (blk - 1760)*256 + threadIdx.x;  // < 64*256
        int o = idx >> 8, j = idx & 255;
        float s = 0.f;
        for (int h=1; h<127; h++) s += mlw[(size_t)(o*128 + h)*256 + j];
        g_Lmid[idx] = s;
    }
}

// ---------------- fused conv+GEMM, split-K, f32x2, double-buffered ----------
// A-builder: 8 contiguous m per thread, uint32 spi loads + shift extraction,
// register-bounded to guarantee 2 CTAs/SM.
__global__ __launch_bounds__(256, 2) void k_gemmF(int which, const float* __restrict__ W,
                                                  const float* __restrict__ bias){
    extern __shared__ char dyn[];
    float (*As)[16][132]      = (float(*)[16][132])(dyn + SM_AS);
    float (*Bs)[16][128]      = (float(*)[16][128])(dyn + SM_BS);
    float (*sP2)[256]         = (float(*)[256])(dyn + SM_P2);
    unsigned char (*spi)[132] = (unsigned char(*)[132])(dyn + SM_SPI);
    float* sbias              = (float*)(dyn + SM_BIAS);

    int tid = threadIdx.x;
    int m0 = blockIdx.x * 128;
    int k0 = blockIdx.y * KC;
    int o0 = k0 >> 7;
    int lk = tid & 15, lm = tid >> 4;
    int mb = lm*8;                   // contiguous 8-m group for the A-builder
    int bj = tid & 127, bk = tid >> 7;
    int tx = tid & 15, ty = tid >> 4;

    const float* P2 = g_P2 + (size_t)which*(3*OC*NPP);
    for (int e = tid; e < 1536; e += 256){
        int kh = e / 512, r = e % 512, oi = r >> 8, p = r & 255;
        sP2[kh*2 + oi][p] = P2[(size_t)kh*OC*NPP + (o0+oi)*NPP + p];
    }
    const unsigned char* piT = g_pi8T + (size_t)which*(HH*BB);
    for (int e = tid; e < 4096; e += 256){
        int h = e >> 5, g = e & 31;
        *(uchar4*)&spi[h][g*4] = *(const uchar4*)(piT + h*BB + m0 + g*4);
    }
    if (tid < 2) sbias[tid] = bias[o0 + tid];
    __syncthreads();

    ull acc[4][8];
    #pragma unroll
    for (int i=0;i<4;i++)
        #pragma unroll
        for (int j=0;j<8;j++) acc[i][j] = 0ull;

    float ra[8], rb[8];
    auto computeA = [&](int t, float* r){
        int k = k0 + t + lk;
        int h = k & 127;
        int oi = (k >> 7) - o0;
        const float* p2a = sP2[0 + oi];
        const float* p2b = sP2[2 + oi];
        const float* p2c = sP2[4 + oi];
        float vb = sbias[oi];
        bool hasA = (h > 0), hasC = (h < 127);
        uint32_t qb0 = *(const uint32_t*)&spi[h][mb];
        uint32_t qb1 = *(const uint32_t*)&spi[h][mb+4];
        uint32_t qa0 = qb0, qa1 = qb1, qc0 = qb0, qc1 = qb1;
        if (hasA){ qa0 = *(const uint32_t*)&spi[h-1][mb]; qa1 = *(const uint32_t*)&spi[h-1][mb+4]; }
        if (hasC){ qc0 = *(const uint32_t*)&spi[h+1][mb]; qc1 = *(const uint32_t*)&spi[h+1][mb+4]; }
        #pragma unroll
        for (int i=0;i<4;i++){
            float v = vb;
            if (hasA) v += p2a[(qa0 >> (8*i)) & 255u];
            v += p2b[(qb0 >> (8*i)) & 255u];
            if (hasC) v += p2c[(qc0 >> (8*i)) & 255u];
            r[i] = v;
        }
        #pragma unroll
        for (int i=0;i<4;i++){
            float v = vb;
            if (hasA) v += p2a[(qa1 >> (8*i)) & 255u];
            v += p2b[(qb1 >> (8*i)) & 255u];
            if (hasC) v += p2c[(qc1 >> (8*i)) & 255u];
            r[4+i] = v;
        }
    };
    auto storeA = [&](int b2, float* r){
        *(float4*)&As[b2][lk][mb]     = make_float4(r[0], r[1], r[2], r[3]);
        *(float4*)&As[b2][lk][mb + 4] = make_float4(r[4], r[5], r[6], r[7]);
    };

    computeA(0, ra);
    #pragma unroll
    for (int i=0;i<8;i++) rb[i] = W[(size_t)(k0 + bk + i*2)*NJ + bj];
    storeA(0, ra);
    #pragma unroll
    for (int i=0;i<8;i++) Bs[0][bk + i*2][bj] = rb[i];
    __syncthreads();

    int buf = 0;
    for (int t = 16; t < KC; t += 16){
        computeA(t, ra);
        #pragma unroll
        for (int i=0;i<8;i++) rb[i] = W[(size_t)(k0 + t + bk + i*2)*NJ + bj];
        #pragma unroll
        for (int kk=0; kk<16; kk++){
            ulonglong2 a01 = *(const ulonglong2*)&As[buf][kk][ty*8];
            ulonglong2 a23 = *(const ulonglong2*)&As[buf][kk][ty*8 + 4];
            float4 b0 = *(const float4*)&Bs[buf][kk][tx*4];
            float4 b1 = *(const float4*)&Bs[buf][kk][64 + tx*4];
            ull ap[4] = { a01.x, a01.y, a23.x, a23.y };
            ull bd[8] = { pk2(b0.x,b0.x), pk2(b0.y,b0.y),
                          pk2(b0.z,b0.z), pk2(b0.w,b0.w),
                          pk2(b1.x,b1.x), pk2(b1.y,b1.y),
                          pk2(b1.z,b1.z), pk2(b1.w,b1.w) };
            #pragma unroll
            for (int i=0;i<4;i++)
                #pragma unroll
                for (int j=0;j<8;j++)
                    ffma2(acc[i][j], ap[i], bd[j]);
        }
        storeA(buf^1, ra);
        #pragma unroll
        for (int i=0;i<8;i++) Bs[buf^1][bk + i*2][bj] = rb[i];
        __syncthreads();
        buf ^= 1;
    }
    #pragma unroll
    for (int kk=0; kk<16; kk++){
        ulonglong2 a01 = *(const ulonglong2*)&As[buf][kk][ty*8];
        ulonglong2 a23 = *(const ulonglong2*)&As[buf][kk][ty*8 + 4];
        float4 b0 = *(const float4*)&Bs[buf][kk][tx*4];
        float4 b1 = *(const float4*)&Bs[buf][kk][64 + tx*4];
        ull ap[4] = { a01.x, a01.y, a23.x, a23.y };
        ull bd[8] = { pk2(b0.x,b0.x), pk2(b0.y,b0.y),
                      pk2(b0.z,b0.z), pk2(b0.w,b0.w),
                      pk2(b1.x,b1.x), pk2(b1.y,b1.y),
                      pk2(b1.z,b1.z), pk2(b1.w,b1.w) };
        #pragma unroll
        for (int i=0;i<4;i++)
            #pragma unroll
            for (int j=0;j<8;j++)
                ffma2(acc[i][j], ap[i], bd[j]);
    }

    float* outp = g_partial + (size_t)blockIdx.y * (BB*NJ);
    #pragma unroll
    for (int i=0;i<4;i++){
        int mlo = m0 + ty*8 + 2*i;
        float rlo[8], rhi[8];
        #pragma unroll
        for (int j=0;j<8;j++) upk2(acc[i][j], rlo[j], rhi[j]);
        *(float4*)&outp[(size_t)mlo*NJ + tx*4]          = make_float4(rlo[0],rlo[1],rlo[2],rlo[3]);
        *(float4*)&outp[(size_t)mlo*NJ + 64 + tx*4]     = make_float4(rlo[4],rlo[5],rlo[6],rlo[7]);
        *(float4*)&outp[(size_t)(mlo+1)*NJ + tx*4]      = make_float4(rhi[0],rhi[1],rhi[2],rhi[3]);
        *(float4*)&outp[(size_t)(mlo+1)*NJ + 64 + tx*4] = make_float4(rhi[4],rhi[5],rhi[6],rhi[7]);
    }
}

// ---------------- mid: reduce + softmax + manip conv + lin + tokens + pair --
__global__ __launch_bounds__(256) void k_mid(const float* __restrict__ bias,
                                             const float* __restrict__ mcb,
                                             const float* __restrict__ mlw,
                                             const float* __restrict__ mlb){
    __shared__ float red[128];
    __shared__ float eo[128];
    __shared__ float rr[192];
    __shared__ unsigned char stok[256];
    int b = blockIdx.x, t = threadIdx.x;
    float v = 0.f;
    if (t < 128){
        float s = bias[t];
        #pragma unroll 8
        for (int kz=0; kz<SPLITK; kz++) s += g_partial[(size_t)(kz*BB + b)*NJ + t];
        v = s;
        red[t] = v;
    }
    __syncthreads();
    for (int st=64; st; st>>=1){ if (t < st) red[t] = fmaxf(red[t], red[t+st]); __syncthreads(); }
    float mx = red[0]; __syncthreads();
    float e = 0.f;
    if (t < 128){ e = expf(v - mx); red[t] = e; }
    __syncthreads();
    for (int st=64; st; st>>=1){ if (t < st) red[t] += red[t+st]; __syncthreads(); }
    if (t < 128) eo[t] = e / red[0];
    __syncthreads();
    if (t < 192){
        int vv = t >> 6, o = t & 63;
        const float* ws = g_Wsum + vv*8192 + o*128;
        float acc = mcb[o];
        for (int c=0;c<128;c++) acc = fmaf(eo[c], ws[c], acc);
        rr[vv*64 + o] = fmaxf(acc, 0.f);
    }
    __syncthreads();
    {
        int j = t;
        float s = mlb[j];
        for (int o=0; o<64; o++){
            s = fmaf(rr[o],       mlw[(size_t)o*32768 + j],          s);
            s = fmaf(rr[64 + o],  g_Lmid[o*256 + j],                 s);
            s = fmaf(rr[128 + o], mlw[(size_t)o*32768 + 32512 + j],  s);
        }
        int tk = (int)floorf(fabsf(s) * 100.0f);
        stok[j] = (unsigned char)(tk % VV);
    }
    __syncthreads();
    if (t < 128)
        g_pi8T[HH*BB + t*BB + b] = (unsigned char)(stok[2*t]*VV + stok[2*t+1]);
}

// ---------------- friend: reduce + final linear + softmax -------------------
__global__ void k_redlin2(const float* __restrict__ bias, const float* __restrict__ w2,
                          const float* __restrict__ b2, float* __restrict__ out){
    __shared__ float f[128];
    int b = blockIdx.x, t = threadIdx.x;
    float s = bias[t];
    #pragma unroll 8
    for (int kz=0; kz<SPLITK; kz++) s += g_partial[(size_t)(kz*BB + b)*NJ + t];
    f[t] = s; __syncthreads();
    if (t < 32){
        float logit = -INFINITY;
        if (t < VV){
            logit = b2[t];
            for (int j=0; j<128; j++) logit = fmaf(f[j], w2[j*VV + t], logit);
        }
        float mx = logit;
        for (int off=16; off; off>>=1) mx = fmaxf(mx, __shfl_xor_sync(0xffffffffu, mx, off));
        float e = (t < VV) ? expf(logit - mx) : 0.f;
        float sm = e;
        for (int off=16; off; off>>=1) sm += __shfl_xor_sync(0xffffffffu, sm, off);
        if (t < VV) out[b*VV + t] = e / sm;
    }
}

// ---------------- launch ----------------------------------------------------
extern "C" void kernel_launch(void* const* d_in, const int* in_sizes, int n_in,
                              void* d_out, int out_size){
    const int*   x    = (const int*)  d_in[0];
    const float* eemb = (const float*)d_in[1];
    const float* ecw  = (const float*)d_in[2];
    const float* ecb  = (const float*)d_in[3];
    const float* elw  = (const float*)d_in[4];
    const float* elb  = (const float*)d_in[5];
    // d_in[6] rand_proj: dead (fog_of_war == identity permutation)
    const float* mcw  = (const float*)d_in[7];
    const float* mcb  = (const float*)d_in[8];
    const float* mlw  = (const float*)d_in[9];
    const float* mlb  = (const float*)d_in[10];
    const float* femb = (const float*)d_in[11];
    const float* fcw  = (const float*)d_in[12];
    const float* fcb  = (const float*)d_in[13];
    const float* flw1 = (const float*)d_in[14];
    const float* flb1 = (const float*)d_in[15];
    const float* flw2 = (const float*)d_in[16];
    const float* flb2 = (const float*)d_in[17];
    float* out = (float*)d_out;

    cudaFuncSetAttribute(k_gemmF, cudaFuncAttributeMaxDynamicSharedMemorySize, SM_TOTAL);

    k_poolT2<<<(2*EMBD*NPP)/256, 256>>>(eemb, femb);           // 1
    k_pbuild2<<<dim3(32,4,2), 512>>>(ecw, fcw);                // 2
    k_prep<<<1824, 256>>>(x, mcw, mlw);                        // 3

    k_gemmF<<<dim3(2, SPLITK), 256, SM_TOTAL>>>(0, elw, ecb);  // 4 <- profiled
    k_mid<<<BB, 256>>>(elb, mcb, mlw, mlb);                    // 5

    k_gemmF<<<dim3(2, SPLITK), 256, SM_TOTAL>>>(1, flw1, fcb); // 6
    k_redlin2<<<BB, 128>>>(flb1, flw2, flb2, out);             // 7
}